// round 16
// baseline (speedup 1.0000x reference)
#include <cuda_runtime.h>
#include <math.h>

// TemplatePointwiseAttention fused kernel, fp32, warp-per-8-pairs.
// Shapes: B=1, T=4, L=384, c_z=128, c_t=64, H=4, C=16.
//
// R13 stage code (310us, scratch-minimized) at NP=8 with occupancy kept:
// WARPS=2 (64 thr), 26.9KB static smem -> 8 blocks/SM (reg-limited) =
// 16 warps/SM, same as R3/R13. Weight LDGs amortize over 8 pairs
// (weight wf/pair 192 -> 112). Register-heavy middle (t-LN / r / logits / u)
// runs in 2 batches of 4 pairs to keep arrays at 32 regs.

namespace {
constexpr int L_ = 384;
constexpr int NPAIR = L_ * L_;        // 147456
constexpr int NP = 8;                 // pairs per warp iteration (8 | 384)
constexpr int NB = NPAIR / NP;        // 18432
constexpr int WARPS = 2;
constexpr int NTHREADS = WARPS * 32;  // 64
constexpr int GRID = 152 * 8;         // 1216 -> 8 blocks/SM

// per-pair scratch (floats):
//   [0..271]   u_s  (4 x 68)   (zn[128] overlays before u is written)
//   [272..335] q_s  (64)
//   [336..351] at_s (16)
//   [352..415] o_s  (64)
constexpr int U_OFF = 0;
constexpr int Q_OFF = 272;
constexpr int A_OFF = 336;
constexpr int O_OFF = 352;
constexpr int SCR_P = 420;
constexpr int SCR_W = NP * SCR_P;                    // 3360 per warp
constexpr int SMEM_FLOATS = WARPS * SCR_W;           // 6720 -> 26880 B

__device__ float g_WkT[64 * 64];   // WkT[c][m] = Wk[m][c]

__device__ __forceinline__ float4 fma4(float s, float4 w, float4 a) {
    a.x = fmaf(s, w.x, a.x); a.y = fmaf(s, w.y, a.y);
    a.z = fmaf(s, w.z, a.z); a.w = fmaf(s, w.w, a.w);
    return a;
}
__device__ __forceinline__ float4 ldcs4(const float* p) { return __ldcs((const float4*)p); }
} // namespace

__global__ void tpa_prep(const float* __restrict__ Wk) {
    int idx = blockIdx.x * blockDim.x + threadIdx.x;
    if (idx < 4096) {
        int m = idx >> 6, c = idx & 63;
        g_WkT[c * 64 + m] = Wk[idx];
    }
}

__global__ __launch_bounds__(NTHREADS, 8) void tpa_fused(
    const float* __restrict__ tin,   // [4,384,384,64]
    const float* __restrict__ zin,   // [384,384,128]
    const float* __restrict__ mask,  // [4,384]
    const float* __restrict__ zg_, const float* __restrict__ zb_,
    const float* __restrict__ tg_, const float* __restrict__ tb_,
    const float* __restrict__ Wq,    // [128,64]
    const float* __restrict__ Wv,    // [64,64]
    const float* __restrict__ Wo,    // [64,128]
    const float* __restrict__ bo,    // [128]
    float* __restrict__ out)         // [384,384,128]
{
    __shared__ float sm[SMEM_FLOATS];
    const int tid  = threadIdx.x;
    const int warp = tid >> 5, lane = tid & 31;
    float* scr = sm + warp * SCR_W;

    const float4 zg = *(const float4*)(zg_ + lane * 4);
    const float4 zb = *(const float4*)(zb_ + lane * 4);
    const float tgA = tg_[lane], tgB = tg_[lane + 32];
    const float tbA = tb_[lane], tbB = tb_[lane + 32];
    const float4 bo4 = *(const float4*)(bo + lane * 4);

    const int idx16 = lane & 15;
    const int t_of  = idx16 >> 2;    // template idx for this lane's logit
    const int h_of  = idx16 & 3;     // head idx
    const int h_o   = lane >> 3;     // head owned in o-stage (n = 2*lane)
    const bool l3 = (lane >> 3) & 1, l2 = (lane >> 2) & 1;
    const bool l1 = (lane >> 1) & 1, l0 = lane & 1;

    const int gw = blockIdx.x * WARPS + warp;
    const int nw = GRID * WARPS;

    for (int b = gw; b < NB; b += nw) {
        const int p0 = b * NP;
        const int i  = p0 / L_;          // all 8 pairs share row i (8 | 384)
        const int j0 = p0 - i * L_;

        // ---- z loads + LN (8 pairs); zn stored into U region ----
        #pragma unroll
        for (int k = 0; k < NP; k++) {
            float4 zv = ldcs4(zin + (size_t)(p0 + k) * 128 + lane * 4);
            float s  = zv.x + zv.y + zv.z + zv.w;
            float ss = zv.x * zv.x + zv.y * zv.y + zv.z * zv.z + zv.w * zv.w;
            #pragma unroll
            for (int o = 16; o > 0; o >>= 1) {
                s  += __shfl_xor_sync(0xffffffffu, s,  o);
                ss += __shfl_xor_sync(0xffffffffu, ss, o);
            }
            float mu   = s * (1.0f / 128.0f);
            float rstd = rsqrtf(fmaf(ss, 1.0f / 128.0f, -mu * mu) + 1e-5f);
            float4 znv;
            znv.x = (zv.x - mu) * rstd * zg.x + zb.x;
            znv.y = (zv.y - mu) * rstd * zg.y + zb.y;
            znv.z = (zv.z - mu) * rstd * zg.z + zb.z;
            znv.w = (zv.w - mu) * rstd * zg.w + zb.w;
            *(float4*)(scr + k * SCR_P + U_OFF + lane * 4) = znv;
        }
        __syncwarp();

        // ---- q[n] = zn . Wq[:,n]; lane owns n=2l,2l+1; Wq amortized x8 ----
        {
            float2 qacc[NP];
            #pragma unroll
            for (int k = 0; k < NP; k++) qacc[k] = make_float2(0.f, 0.f);
            const float* wq = Wq + 2 * lane;
            #pragma unroll 4
            for (int m = 0; m < 128; m += 4) {
                const float* w = wq + m * 64;
                float2 w0 = *(const float2*)(w);
                float2 w1 = *(const float2*)(w + 64);
                float2 w2 = *(const float2*)(w + 128);
                float2 w3 = *(const float2*)(w + 192);
                #pragma unroll
                for (int k = 0; k < NP; k++) {
                    float4 z4 = *(const float4*)(scr + k * SCR_P + U_OFF + m);  // bcast
                    qacc[k].x = fmaf(z4.x, w0.x, fmaf(z4.y, w1.x,
                                fmaf(z4.z, w2.x, fmaf(z4.w, w3.x, qacc[k].x))));
                    qacc[k].y = fmaf(z4.x, w0.y, fmaf(z4.y, w1.y,
                                fmaf(z4.z, w2.y, fmaf(z4.w, w3.y, qacc[k].y))));
                }
            }
            #pragma unroll
            for (int k = 0; k < NP; k++)
                *(float2*)(scr + k * SCR_P + Q_OFF + 2 * lane) = qacc[k];
        }
        __syncwarp();

        // ==== middle stages in 2 batches of 4 pairs (register arrays small) ====
        const float pm_i = mask[t_of * L_ + i];
        #pragma unroll
        for (int bt = 0; bt < 2; bt++) {
            const int kb0 = bt * 4;

            // t loads into registers (lane owns m=lane and m=lane+32)
            float tn0[4][4], tn1[4][4];
            #pragma unroll
            for (int kb = 0; kb < 4; kb++)
                #pragma unroll
                for (int t = 0; t < 4; t++) {
                    const float* tp = tin + ((size_t)(t * L_ + i) * L_ + (j0 + kb0 + kb)) * 64;
                    tn0[kb][t] = __ldcs(tp + lane);
                    tn1[kb][t] = __ldcs(tp + lane + 32);
                }

            // r[h][m] in registers (m=lane, lane+32)
            float r0[4][4], r1[4][4];
            #pragma unroll
            for (int kb = 0; kb < 4; kb++)
                #pragma unroll
                for (int h = 0; h < 4; h++) { r0[kb][h] = 0.f; r1[kb][h] = 0.f; }
            #pragma unroll
            for (int h = 0; h < 4; h++) {
                #pragma unroll
                for (int cc = 0; cc < 16; cc += 4) {
                    const float* wk = g_WkT + (h * 16 + cc) * 64;
                    float w0l = wk[lane],        w0h = wk[lane + 32];
                    float w1l = wk[64 + lane],   w1h = wk[64 + lane + 32];
                    float w2l = wk[128 + lane],  w2h = wk[128 + lane + 32];
                    float w3l = wk[192 + lane],  w3h = wk[192 + lane + 32];
                    #pragma unroll
                    for (int kb = 0; kb < 4; kb++) {
                        float4 q4 = *(const float4*)(scr + (kb0 + kb) * SCR_P + Q_OFF + h * 16 + cc);
                        r0[kb][h] = fmaf(q4.x, w0l, fmaf(q4.y, w1l,
                                    fmaf(q4.z, w2l, fmaf(q4.w, w3l, r0[kb][h]))));
                        r1[kb][h] = fmaf(q4.x, w0h, fmaf(q4.y, w1h,
                                    fmaf(q4.z, w2h, fmaf(q4.w, w3h, r1[kb][h]))));
                    }
                }
            }

            // t layernorms in registers
            #pragma unroll
            for (int kb = 0; kb < 4; kb++)
                #pragma unroll
                for (int t = 0; t < 4; t++) {
                    float a = tn0[kb][t], c2 = tn1[kb][t];
                    float s  = a + c2;
                    float ss = a * a + c2 * c2;
                    #pragma unroll
                    for (int o = 16; o > 0; o >>= 1) {
                        s  += __shfl_xor_sync(0xffffffffu, s,  o);
                        ss += __shfl_xor_sync(0xffffffffu, ss, o);
                    }
                    float mu   = s * (1.0f / 64.0f);
                    float rstd = rsqrtf(fmaf(ss, 1.0f / 64.0f, -mu * mu) + 1e-5f);
                    tn0[kb][t] = (a  - mu) * rstd * tgA + tbA;
                    tn1[kb][t] = (c2 - mu) * rstd * tgB + tbB;
                }

            // logits: register partials + butterfly shfl reduction; softmax
            #pragma unroll
            for (int kb = 0; kb < 4; kb++) {
                const int k = kb0 + kb;
                float P[16];
                #pragma unroll
                for (int t = 0; t < 4; t++)
                    #pragma unroll
                    for (int h = 0; h < 4; h++)
                        P[t * 4 + h] = fmaf(tn0[kb][t], r0[kb][h], tn1[kb][t] * r1[kb][h]);

                float Q[8];
                #pragma unroll
                for (int j = 0; j < 8; j++) {
                    float snd = l3 ? P[j] : P[j + 8];
                    float kp  = l3 ? P[j + 8] : P[j];
                    Q[j] = kp + __shfl_xor_sync(0xffffffffu, snd, 8);
                }
                float R4[4];
                #pragma unroll
                for (int j = 0; j < 4; j++) {
                    float snd = l2 ? Q[j] : Q[j + 4];
                    float kp  = l2 ? Q[j + 4] : Q[j];
                    R4[j] = kp + __shfl_xor_sync(0xffffffffu, snd, 4);
                }
                float S2[2];
                #pragma unroll
                for (int j = 0; j < 2; j++) {
                    float snd = l1 ? R4[j] : R4[j + 2];
                    float kp  = l1 ? R4[j + 2] : R4[j];
                    S2[j] = kp + __shfl_xor_sync(0xffffffffu, snd, 2);
                }
                float snd = l0 ? S2[0] : S2[1];
                float kp  = l0 ? S2[1] : S2[0];
                float T = kp + __shfl_xor_sync(0xffffffffu, snd, 1);
                T += __shfl_xor_sync(0xffffffffu, T, 16);   // fold lane halves

                float logit = T * 0.25f;                    // 1/sqrt(C)
                float pm = pm_i * mask[t_of * L_ + j0 + k];
                logit = (pm == 0.0f) ? -1e9f : logit;

                float mx = fmaxf(logit, __shfl_xor_sync(0xffffffffu, logit, 4));
                mx = fmaxf(mx, __shfl_xor_sync(0xffffffffu, mx, 8));
                float e = __expf(logit - mx);
                float den = e + __shfl_xor_sync(0xffffffffu, e, 4);
                den += __shfl_xor_sync(0xffffffffu, den, 8);
                float attn = __fdividef(e, den) * pm;
                float s2 = attn + __shfl_xor_sync(0xffffffffu, attn, 4);
                s2 += __shfl_xor_sync(0xffffffffu, s2, 8);
                attn = __fdividef(attn, fmaxf(s2, 1e-8f));
                scr[k * SCR_P + A_OFF + t_of * 4 + h_of] = attn;  // halves same
            }
            __syncwarp();

            // u[h][m] in registers (attn via bcast), store to U region
            #pragma unroll
            for (int kb = 0; kb < 4; kb++) {
                const int k = kb0 + kb;
                float u00 = 0.f, u01 = 0.f, u02 = 0.f, u03 = 0.f;
                float u10 = 0.f, u11 = 0.f, u12 = 0.f, u13 = 0.f;
                #pragma unroll
                for (int t = 0; t < 4; t++) {
                    float4 av = *(const float4*)(scr + k * SCR_P + A_OFF + t * 4);
                    float a = tn0[kb][t], c2 = tn1[kb][t];
                    u00 = fmaf(av.x, a, u00); u10 = fmaf(av.x, c2, u10);
                    u01 = fmaf(av.y, a, u01); u11 = fmaf(av.y, c2, u11);
                    u02 = fmaf(av.z, a, u02); u12 = fmaf(av.z, c2, u12);
                    u03 = fmaf(av.w, a, u03); u13 = fmaf(av.w, c2, u13);
                }
                float* pk = scr + k * SCR_P + U_OFF;
                pk[lane]            = u00;  pk[lane + 32]       = u10;
                pk[68 + lane]       = u01;  pk[68 + lane + 32]  = u11;
                pk[136 + lane]      = u02;  pk[136 + lane + 32] = u12;
                pk[204 + lane]      = u03;  pk[204 + lane + 32] = u13;
            }
            __syncwarp();
        }

        // ---- o[n] = u[h(n)] . Wv[:,n]; lane owns n=2l,2l+1; Wv amortized x8 ----
        {
            float2 oacc[NP];
            #pragma unroll
            for (int k = 0; k < NP; k++) oacc[k] = make_float2(0.f, 0.f);
            const float* wv = Wv + 2 * lane;
            #pragma unroll 4
            for (int m = 0; m < 64; m += 4) {
                const float* w = wv + m * 64;
                float2 w0 = *(const float2*)(w);
                float2 w1 = *(const float2*)(w + 64);
                float2 w2 = *(const float2*)(w + 128);
                float2 w3 = *(const float2*)(w + 192);
                #pragma unroll
                for (int k = 0; k < NP; k++) {
                    float4 u4 = *(const float4*)(scr + k * SCR_P + U_OFF + h_o * 68 + m);
                    oacc[k].x = fmaf(u4.x, w0.x, fmaf(u4.y, w1.x,
                                fmaf(u4.z, w2.x, fmaf(u4.w, w3.x, oacc[k].x))));
                    oacc[k].y = fmaf(u4.x, w0.y, fmaf(u4.y, w1.y,
                                fmaf(u4.z, w2.y, fmaf(u4.w, w3.y, oacc[k].y))));
                }
            }
            #pragma unroll
            for (int k = 0; k < NP; k++)
                *(float2*)(scr + k * SCR_P + O_OFF + 2 * lane) = oacc[k];
        }
        __syncwarp();

        // ---- out[j'] = o . Wo[:,j'] + bo; lane owns j'=4l..4l+3; Wo x8 ----
        {
            float4 acc[NP];
            #pragma unroll
            for (int k = 0; k < NP; k++) acc[k] = bo4;
            const float* wo = Wo + 4 * lane;
            #pragma unroll 4
            for (int n = 0; n < 64; n += 4) {
                const float* w = wo + n * 128;
                float4 w0 = *(const float4*)(w);
                float4 w1 = *(const float4*)(w + 128);
                float4 w2 = *(const float4*)(w + 256);
                float4 w3 = *(const float4*)(w + 384);
                #pragma unroll
                for (int k = 0; k < NP; k++) {
                    float4 o4 = *(const float4*)(scr + k * SCR_P + O_OFF + n);  // bcast
                    acc[k] = fma4(o4.x, w0, acc[k]);
                    acc[k] = fma4(o4.y, w1, acc[k]);
                    acc[k] = fma4(o4.z, w2, acc[k]);
                    acc[k] = fma4(o4.w, w3, acc[k]);
                }
            }
            #pragma unroll
            for (int k = 0; k < NP; k++)
                __stcs((float4*)(out + (size_t)(p0 + k) * 128 + 4 * lane), acc[k]);
        }
        __syncwarp();   // scratch reuse barrier before next block
    }
}

extern "C" void kernel_launch(void* const* d_in, const int* in_sizes, int n_in,
                              void* d_out, int out_size) {
    (void)in_sizes; (void)n_in; (void)out_size;
    tpa_prep<<<16, 256>>>((const float*)d_in[8]);   // Wk
    tpa_fused<<<GRID, NTHREADS>>>(
        (const float*)d_in[0],  // t
        (const float*)d_in[1],  // z
        (const float*)d_in[2],  // template_mask
        (const float*)d_in[3],  // z_ln_g
        (const float*)d_in[4],  // z_ln_b
        (const float*)d_in[5],  // t_ln_g
        (const float*)d_in[6],  // t_ln_b
        (const float*)d_in[7],  // Wq
        (const float*)d_in[9],  // Wv
        (const float*)d_in[10], // Wo
        (const float*)d_in[11], // bo
        (float*)d_out);
}